// round 17
// baseline (speedup 1.0000x reference)
#include <cuda_runtime.h>
#include <cuda_fp16.h>
#include <cstdint>

// Fixed problem shape
#define BB   8
#define CC   256
#define HH   64
#define WWD  64
#define OO   256
#define KKT  9
#define HWSZ 4096

#define TP   128         // pixel tile per GEMM CTA
#define NT   512         // 16 warps: 4 M-warps x 4 N-warps
#define NITER 18         // 2 c-chunks of 128 x 9 kpos

// ---- GEMM smem layout (bytes): A 2x64KB + B 2x32KB = 192KB ----
#define SM_A    0
#define SM_B    131072
#define SMEM_TOTAL 196608

// Packed bilinear tap
struct __align__(16) Tap {
    unsigned short idx[4];
    __half2 w01;
    __half2 w23;
};

// ---- device scratch ----
__device__ __align__(16) __half g_wh[KKT * OO * CC];                       // [k][o][c] fp16
__device__ __align__(16) __half g_xn[(size_t)BB * HWSZ * CC];              // NHWC fp16
__device__ __align__(16) __half g_cols[(size_t)BB * KKT * HWSZ * CC];      // im2col, 151MB

// ---------------- merged prep kernel ----------------
#define PREP_WBLK 2304
#define PREP_XBLK 8192
__global__ void prep_all(const float* __restrict__ w, const float* __restrict__ x) {
    __shared__ float tile[32][33];
    if (blockIdx.x < PREP_WBLK) {
        const int o = blockIdx.x & 255;
        const int k = blockIdx.x >> 8;
        const int c = threadIdx.x;
        float v = w[((size_t)o * CC + c) * KKT + k];
        g_wh[((size_t)k * OO + o) * CC + c] = __float2half_rn(v);
    } else {
        const int bidx = blockIdx.x - PREP_WBLK;
        const int bb  = bidx >> 10;
        const int rem = bidx & 1023;
        const int hw0 = (rem & 127) * 32;
        const int c0  = (rem >> 7) * 32;
        const int tx = threadIdx.x & 31;
        const int ty = threadIdx.x >> 5;
        const float* src = x + (size_t)bb * CC * HWSZ;
        #pragma unroll
        for (int i = 0; i < 32; i += 8)
            tile[ty + i][tx] = src[(size_t)(c0 + ty + i) * HWSZ + hw0 + tx];
        __syncthreads();
        __half* dst = g_xn + (size_t)bb * HWSZ * CC;
        #pragma unroll
        for (int i = 0; i < 32; i += 8)
            dst[(size_t)(hw0 + ty + i) * CC + c0 + tx] = __float2half_rn(tile[tx][ty + i]);
    }
}

// ---------------- im2col v2: per-block 64 px x ALL 9 kpos (L1 reuse) ----------------
#define IC2_PX 64
__global__ __launch_bounds__(256)
void im2col2_kernel(const float* __restrict__ offs, const float* __restrict__ mask) {
    __shared__ Tap taps[KKT * IC2_PX];     // 9216 B
    const int tid  = threadIdx.x;
    const int hw0  = blockIdx.x * IC2_PX;
    const int bb   = blockIdx.y;

    // taps for all 9 kpos of this 64-px tile
    for (int i = tid; i < KKT * IC2_PX; i += 256) {
        const int kpos = i >> 6;
        const int p    = i & 63;
        const int hw = hw0 + p;
        const int h  = hw >> 6;
        const int w  = hw & 63;
        const float oy = offs[((size_t)bb * 18 + kpos * 2 + 0) * HWSZ + hw];
        const float ox = offs[((size_t)bb * 18 + kpos * 2 + 1) * HWSZ + hw];
        const float m  = mask[((size_t)bb * KKT + kpos) * HWSZ + hw];

        const float py = (float)(h - 1 + kpos / 3) + oy;
        const float px = (float)(w - 1 + kpos % 3) + ox;
        const float fy = floorf(py), fx = floorf(px);
        const int y0 = (int)fy, x0 = (int)fx;
        const float ly = py - fy, lx = px - fx;
        const float hy = 1.0f - ly, hx = 1.0f - lx;

        const bool vy0 = (y0 >= 0) && (y0 < HH);
        const bool vy1 = (y0 + 1 >= 0) && (y0 + 1 < HH);
        const bool vx0 = (x0 >= 0) && (x0 < WWD);
        const bool vx1 = (x0 + 1 >= 0) && (x0 + 1 < WWD);
        const int cy0 = min(max(y0, 0), HH - 1);
        const int cy1 = min(max(y0 + 1, 0), HH - 1);
        const int cx0 = min(max(x0, 0), WWD - 1);
        const int cx1 = min(max(x0 + 1, 0), WWD - 1);

        Tap t;
        t.idx[0] = (unsigned short)(cy0 * WWD + cx0);
        t.idx[1] = (unsigned short)(cy0 * WWD + cx1);
        t.idx[2] = (unsigned short)(cy1 * WWD + cx0);
        t.idx[3] = (unsigned short)(cy1 * WWD + cx1);
        const float w0v = (vy0 && vx0) ? hy * hx * m : 0.0f;
        const float w1v = (vy0 && vx1) ? hy * lx * m : 0.0f;
        const float w2v = (vy1 && vx0) ? ly * hx * m : 0.0f;
        const float w3v = (vy1 && vx1) ? ly * lx * m : 0.0f;
        t.w01 = __floats2half2_rn(w0v, w1v);
        t.w23 = __floats2half2_rn(w2v, w3v);
        taps[i] = t;
    }
    __syncthreads();

    const int wid  = tid >> 5;
    const int lane = tid & 31;
    const __half* __restrict__ xb = g_xn + (size_t)bb * HWSZ * CC + lane * 8;

    for (int kpos = 0; kpos < KKT; ++kpos) {
        __half* __restrict__ outp = g_cols
            + ((size_t)(bb * KKT + kpos) * HWSZ + hw0) * CC;
        #pragma unroll
        for (int e = 0; e < 8; ++e) {
            const int p = wid * 8 + e;
            const Tap t = taps[kpos * IC2_PX + p];
            uint4 c0 = *(const uint4*)(xb + (size_t)t.idx[0] * CC);
            uint4 c1 = *(const uint4*)(xb + (size_t)t.idx[1] * CC);
            uint4 c2 = *(const uint4*)(xb + (size_t)t.idx[2] * CC);
            uint4 c3 = *(const uint4*)(xb + (size_t)t.idx[3] * CC);
            const __half2 h0 = __low2half2(t.w01);
            const __half2 h1 = __high2half2(t.w01);
            const __half2 h2 = __low2half2(t.w23);
            const __half2 h3 = __high2half2(t.w23);
            const __half2* p0 = (const __half2*)&c0;
            const __half2* p1 = (const __half2*)&c1;
            const __half2* p2 = (const __half2*)&c2;
            const __half2* p3 = (const __half2*)&c3;
            uint4 v;
            __half2* pv = (__half2*)&v;
            #pragma unroll
            for (int j = 0; j < 4; ++j) {
                __half2 r = __hmul2(h0, p0[j]);
                r = __hfma2(h1, p1[j], r);
                r = __hfma2(h2, p2[j], r);
                r = __hfma2(h3, p3[j], r);
                pv[j] = r;
            }
            *(uint4*)(outp + (size_t)p * CC + lane * 8) = v;
        }
    }
}

// ---------------- helpers ----------------
__device__ __forceinline__ uint32_t s2u(const void* p) {
    uint32_t r;
    asm("{ .reg .u64 t; cvta.to.shared.u64 t, %1; cvt.u32.u64 %0, t; }" : "=r"(r) : "l"(p));
    return r;
}
__device__ __forceinline__ uint32_t sw128(uint32_t off) {
    return off ^ ((off >> 3) & 0x70);
}
__device__ __forceinline__ void ldsm_x4(uint32_t addr, uint32_t& r0, uint32_t& r1,
                                        uint32_t& r2, uint32_t& r3) {
    asm volatile("ldmatrix.sync.aligned.m8n8.x4.shared.b16 {%0,%1,%2,%3}, [%4];"
                 : "=r"(r0), "=r"(r1), "=r"(r2), "=r"(r3) : "r"(addr));
}
__device__ __forceinline__ void mma_fp16(float* d, const uint32_t* a, uint32_t b0, uint32_t b1) {
    asm volatile("mma.sync.aligned.m16n8k16.row.col.f32.f16.f16.f32 "
                 "{%0,%1,%2,%3}, {%4,%5,%6,%7}, {%8,%9}, {%0,%1,%2,%3};"
                 : "+f"(d[0]), "+f"(d[1]), "+f"(d[2]), "+f"(d[3])
                 : "r"(a[0]), "r"(a[1]), "r"(a[2]), "r"(a[3]), "r"(b0), "r"(b1));
}
__device__ __forceinline__ void cp16(uint32_t dst, const void* src) {
    asm volatile("cp.async.cg.shared.global [%0], [%1], 16;" :: "r"(dst), "l"(src) : "memory");
}
__device__ __forceinline__ void cp_commit() { asm volatile("cp.async.commit_group;" ::: "memory"); }
__device__ __forceinline__ void cp_wait0()  { asm volatile("cp.async.wait_group 0;"  ::: "memory"); }

extern __shared__ char smraw[];

// ---------------- GEMM kernel: out = W x cols (all operands staged via cp.async) ----------------
__global__ __launch_bounds__(NT, 1)
void dcn_gemm_kernel(const float* __restrict__ bias, float* __restrict__ out) {
    const int tid  = threadIdx.x;
    const int lane = tid & 31;
    const int wid  = tid >> 5;
    const int warpM = wid >> 2;
    const int warpN = wid & 3;
    const int bb   = blockIdx.y;
    const int hw0  = blockIdx.x * TP;

    const uint32_t uA = s2u(smraw + SM_A);
    const uint32_t uB = s2u(smraw + SM_B);

    float acc[4][4][4];
    #pragma unroll
    for (int mf = 0; mf < 4; ++mf)
        #pragma unroll
        for (int nf = 0; nf < 4; ++nf)
            #pragma unroll
            for (int r = 0; r < 4; ++r) acc[mf][nf][r] = 0.0f;

    auto stageA = [&](int jt, int buf) {
        const int kpos = jt % KKT;
        const int c0   = (jt / KKT) * 128;
        const int q = tid & 7;
        const int r = tid >> 3;          // 0..63
        const uint32_t abase = uA + buf * 65536;
        const uint32_t swoff = sw128((uint32_t)(r * 128 + q * 16));
        #pragma unroll
        for (int rr = 0; rr < 4; ++rr) {
            const int row = r + rr * 64;
            const __half* src = g_wh + ((size_t)kpos * OO + row) * CC + c0 + q * 8;
            cp16(abase + swoff + rr * 64 * 128, src);
            cp16(abase + 32768 + swoff + rr * 64 * 128, src + 64);
        }
    };
    auto stageB = [&](int jt, int buf) {
        const int kpos = jt % KKT;
        const int c0   = (jt / KKT) * 128;
        const __half* colb = g_cols
            + ((size_t)(bb * KKT + kpos) * HWSZ + hw0) * CC + c0;
        const uint32_t bbase = uB + buf * 32768;
        #pragma unroll
        for (int rr = 0; rr < 4; ++rr) {
            const int m = tid + rr * NT;          // 0..2047
            const int half = m >> 10;
            const int pp   = (m >> 3) & 127;
            const int q    = m & 7;
            const __half* src = colb + (size_t)pp * CC + half * 64 + q * 8;
            cp16(bbase + half * 16384 + sw128((uint32_t)(pp * 128 + q * 16)), src);
        }
    };
    auto mmaKS = [&](int ks, int buf) {
        const int half = ks >> 2;
        const int ksl  = ks & 3;
        const uint32_t abase = uA + buf * 65536 + half * 32768;
        const uint32_t bbase = uB + buf * 32768 + half * 16384;
        uint32_t a[4][4];
        #pragma unroll
        for (int mf = 0; mf < 4; ++mf) {
            const uint32_t off = (uint32_t)((warpM * 64 + mf * 16 + (lane & 15)) * 128
                                            + ksl * 32 + (lane >> 4) * 16);
            ldsm_x4(abase + sw128(off), a[mf][0], a[mf][1], a[mf][2], a[mf][3]);
        }
        uint32_t bfr[4][2];
        #pragma unroll
        for (int pb = 0; pb < 2; ++pb) {
            const uint32_t off = (uint32_t)((warpN * 32 + pb * 16 + (lane & 15)) * 128
                                            + ksl * 32 + (lane >> 4) * 16);
            uint32_t r0, r1, r2, r3;
            ldsm_x4(bbase + sw128(off), r0, r1, r2, r3);
            bfr[pb * 2 + 0][0] = r0; bfr[pb * 2 + 0][1] = r2;
            bfr[pb * 2 + 1][0] = r1; bfr[pb * 2 + 1][1] = r3;
        }
        #pragma unroll
        for (int mf = 0; mf < 4; ++mf)
            #pragma unroll
            for (int nf = 0; nf < 4; ++nf)
                mma_fp16(acc[mf][nf], a[mf], bfr[nf][0], bfr[nf][1]);
    };

    // prologue
    stageA(0, 0);
    stageB(0, 0);
    cp_commit();
    cp_wait0();
    __syncthreads();

    for (int it = 0; it < NITER; ++it) {
        const int buf  = it & 1;
        const bool more = (it + 1 < NITER);
        if (more) { stageA(it + 1, buf ^ 1); stageB(it + 1, buf ^ 1); cp_commit(); }

        #pragma unroll
        for (int j = 0; j < 8; ++j) mmaKS(j, buf);

        if (more) cp_wait0();
        __syncthreads();
    }

    // epilogue: bias add + fp32 stores
    #pragma unroll
    for (int mf = 0; mf < 4; ++mf) {
        const int o0 = warpM * 64 + mf * 16 + (lane >> 2);
        const float bv0 = bias[o0];
        const float bv1 = bias[o0 + 8];
        #pragma unroll
        for (int nf = 0; nf < 4; ++nf) {
            const int p = hw0 + warpN * 32 + nf * 8 + (lane & 3) * 2;
            float* d0 = out + ((size_t)(bb * OO + o0)) * HWSZ + p;
            float* d1 = out + ((size_t)(bb * OO + o0 + 8)) * HWSZ + p;
            float2 v0, v1;
            v0.x = acc[mf][nf][0] + bv0; v0.y = acc[mf][nf][1] + bv0;
            v1.x = acc[mf][nf][2] + bv1; v1.y = acc[mf][nf][3] + bv1;
            *(float2*)d0 = v0;
            *(float2*)d1 = v1;
        }
    }
}

extern "C" void kernel_launch(void* const* d_in, const int* in_sizes, int n_in,
                              void* d_out, int out_size) {
    const float* inp    = (const float*)d_in[0];  // [8,256,64,64]
    const float* offs   = (const float*)d_in[1];  // [8,18,64,64]
    const float* mask   = (const float*)d_in[2];  // [8,9,64,64]
    const float* weight = (const float*)d_in[3];  // [256,256,3,3]
    const float* bias   = (const float*)d_in[4];  // [256]
    float* out = (float*)d_out;                   // [8,256,64,64]

    cudaFuncSetAttribute(dcn_gemm_kernel,
                         cudaFuncAttributeMaxDynamicSharedMemorySize, SMEM_TOTAL);

    prep_all<<<PREP_WBLK + PREP_XBLK, 256>>>(weight, inp);
    im2col2_kernel<<<dim3(HWSZ / IC2_PX, BB), 256>>>(offs, mask);

    dim3 grid(HWSZ / TP, BB);   // (32, 8) = 256 CTAs
    dcn_gemm_kernel<<<grid, NT, SMEM_TOTAL>>>(bias, out);
}